// round 11
// baseline (speedup 1.0000x reference)
#include <cuda_runtime.h>
#include <cstdint>

#define B_ 64
#define T_ 128
#define F_ 1024
#define S_ 512
#define M_ 2048
#define EPS_ 0.45f
#define NB 128
#define NT 1024
#define NSLOT 10
#define FULLM 0xffffffffu

typedef unsigned long long u64;
typedef unsigned u32;
typedef unsigned short u16;
typedef unsigned char u8;

// ---------------- device scratch (static, no allocation) ----------------
__device__ float g_qpool[B_][F_];      // materialized upd_mem_q per step
__device__ float g_upds[B_ * F_];      // precomputed upd_mem_s per step
__device__ float g_updidxs[B_];        // precomputed upd_idx_s per step
__device__ float g_lc0[M_];            // memin[:, -1]
__device__ int   g_flags[B_];          // per-step cond_s
__device__ int   g_flagq0;             // step-0 cond_q
__device__ int   g_scnt[B_];           // per-step chunk arrival count
__device__ int   g_sready[B_];         // step data ready (release flag)
__device__ float4 g_scal4[B_];         // packed {conds, updidxs, upds_l, 0}
__device__ int   g_ticket;             // worker chunk dispenser
__device__ int   g_readyQ;             // memin scan done count
// generic-path (big-G) group arrays
__device__ float g_bgidx[M_];
__device__ float g_bglc[M_];
__device__ u16   g_bgcls[M_];
__device__ u16   g_bgmin[M_];

// ---------------- helpers ----------------
__device__ __forceinline__ float comp_fn(float x, float s) {
    float d  = __fsub_rn(x, s);
    float t  = __fadd_rn(__fmul_rn(0.2f, d), 0.5f);
    float hs = fminf(fmaxf(t, 0.0f), 1.0f);
    return __fsub_rn(0.5f, hs);
}
__device__ __forceinline__ u32 fenc(float x) {
    u32 u = __float_as_uint(x);
    return (u & 0x80000000u) ? ~u : (u | 0x80000000u);
}
__device__ __forceinline__ float fdec(u32 u) {
    u32 v = (u & 0x80000000u) ? (u & 0x7FFFFFFFu) : ~u;
    return __uint_as_float(v);
}
__device__ __forceinline__ u64 pack_gm(u32 venc, u32 gmin) {
    return ((u64)venc << 32) | (u64)(0xffffffffu - gmin);
}
__device__ __forceinline__ const float* cls_ptr(int id,
        const float* __restrict__ memin, const float* __restrict__ states) {
    if (id < 2048) return memin + (size_t)id * F_;
    if (id < 2112) return g_qpool[id - 2048];
    if (id < 2176) return g_upds + (size_t)(id - 2112) * F_;
    return states + ((size_t)(id - 2176) * T_ + (T_ - 1)) * F_;
}

__global__ void k_reset() {
    int t = threadIdx.x;
    if (t < B_) { g_flags[t] = 0; g_scnt[t] = 0; g_sready[t] = 0; }
    if (t == 0) { g_ticket = 0; g_readyQ = 0; g_flagq0 = 0; }
}

// ---------------- persistent kernel ----------------
__global__ void __launch_bounds__(NT, 1) mega(
    const float* __restrict__ states, const float* __restrict__ mr,
    const float* __restrict__ memin, const float* __restrict__ index,
    float* __restrict__ out)
{
    __shared__ float s_cache[NSLOT * F_];       // 40KB class-vector cache
    __shared__ float s_gidx[64], s_glc[64];     // small group arrays (warp path)
    __shared__ u16 s_gcls[64], s_gmin16[64];
    __shared__ u8  s_gslot[64], s_gfill[64];
    __shared__ int   s_tconds, s_scstep;        // smem scalar triple (generic path)
    __shared__ float s_tidx, s_tupl;
    __shared__ u64 s_r64[33];
    __shared__ u32 s_ru[33];
    __shared__ int s_G, s_jt, s_misrc, s_micls, s_cnt, s_tcls, s_tk, s_clsmiS, s_uvok;
    __shared__ float sh_r, s_c, s_imp, s_idxmi, s_lcmi;

    const int bid = blockIdx.x, tid = threadIdx.x;
    const int lane = tid & 31, wid = tid >> 5;

    // ================= WORKERS (bid 1..127) =================
    if (bid != 0) {
        {   // memin scan share + lc0 + flagq0
            const float* s0 = states + (size_t)(T_ - 1) * F_;
            float s0v = s0[tid];
            int start = (bid - 1) * 17, end = min(start + 17, M_);
            int any = 0;
            for (int row = start; row < end; row++) {
                float v = memin[(size_t)row * F_ + tid];
                if (tid == F_ - 1) g_lc0[row] = v;
                any |= (comp_fn(v, s0v) >= EPS_);
            }
            int anyb = __syncthreads_or(any);
            __threadfence();
            __syncthreads();
            if (tid == 0) {
                if (anyb) atomicOr(&g_flagq0, 1);
                __threadfence();
                atomicAdd(&g_readyQ, 1);
            }
        }
        // ticket loop: 512 chunks = 64 steps x 8 col-chunks, in step order
        float* scrA = s_cache; float* scrB = s_cache + NT;
        while (true) {
            if (tid == 0) s_tk = atomicAdd(&g_ticket, 1);
            __syncthreads();
            int t = s_tk;
            if (t >= 512) break;
            const int b = t >> 3, ch = t & 7;
            const int col = ch * 128 + (tid & 127);
            const int rg = tid >> 7;   // 8 row groups of 64 rows
            const float* srow = states + ((size_t)b * T_ + (T_ - 1)) * F_;
            const float sf = srow[col];
            const float* mrb = mr + (size_t)b * S_ * F_;
            float mx = -3.402823466e38f, ma = 0.0f; int any2 = 0;
            #pragma unroll 8
            for (int ri = rg; ri < S_; ri += 8) {
                float v  = mrb[(size_t)ri * F_ + col];
                float cp = comp_fn(v, sf);
                any2 |= (cp >= EPS_);
                ma = fmaxf(ma, fabsf(cp));
                mx = fmaxf(mx, v);
            }
            scrA[tid] = mx; scrB[tid] = ma;
            int anyc = __syncthreads_or(any2);
            if (tid < 128) {
                float amx = scrA[tid], ama = scrB[tid];
                #pragma unroll
                for (int g = 1; g < 8; g++) {
                    amx = fmaxf(amx, scrA[g * 128 + tid]);
                    ama = fmaxf(ama, scrB[g * 128 + tid]);
                }
                int cc = ch * 128 + tid;
                float cs = __fmul_rn(sqrtf((float)S_), ama);
                g_upds[(size_t)b * F_ + cc] =
                    __fadd_rn(__fmul_rn(amx, cs), __fmul_rn(sf, __fsub_rn(1.0f, cs)));
                if (cc == F_ - 1) {
                    float mr0 = mrb[F_ - 1];   // mr[0, -1]
                    g_updidxs[b] = __fadd_rn(__fmul_rn(mr0, cs),
                                             __fmul_rn(sf, __fsub_rn(1.0f, cs)));
                }
            }
            __threadfence();
            __syncthreads();
            if (tid == 0) {
                if (anyc) atomicOr(&g_flags[b], 1);
                __threadfence();
                int done = atomicAdd(&g_scnt[b], 1);
                if (done == 7) {
                    __threadfence();
                    float4 q;
                    q.x = __int_as_float(*(volatile int*)&g_flags[b]);
                    q.y = *(volatile float*)&g_updidxs[b];
                    q.z = *(volatile float*)&g_upds[(size_t)b * F_ + F_ - 1];
                    q.w = 0.0f;
                    g_scal4[b] = q;
                    __threadfence();
                    atomicExch(&g_sready[b], 1);
                }
            }
            __syncthreads();
        }
        return;
    }

    // ================= CONSUMER (block 0) =================
    if (tid == 0) {
        volatile int* rq = &g_readyQ;
        while (*rq < NB - 1) { }
        volatile int* rs = &g_sready[0];
        while (!*rs) { }
        __threadfence();
        float4 q0 = *(const float4*)&g_scal4[0];
        s_tconds = __float_as_int(q0.x);
        s_tidx   = q0.y;
        s_tupl   = q0.z;
        s_scstep = 0;
        s_G = M_;
    }
    __syncthreads();
    #pragma unroll
    for (int k = 0; k < 2; k++) {
        int m = tid + k * 1024;
        g_bgidx[m] = index[m];
        g_bglc[m]  = g_lc0[m];
        g_bgcls[m] = (u16)m;
        g_bgmin[m] = (u16)m;
    }
    float sv = states[(size_t)(T_ - 1) * F_ + tid];
    if (tid == F_ - 1) sh_r = sv;
    int condq = g_flagq0;
    float uv = g_upds[tid];
    // warp-0 scalar prefetch pipeline regs (valid only in warp 0)
    int p_have = 0, p_conds = 0;
    float p_idx = 0.f, p_upl = 0.f;
    int uvh = 1;   // uv for the current step already loaded & valid
    __syncthreads();

    for (int b = 0; b < B_; b++) {
        const float* snrow = states + ((size_t)((b < B_ - 1) ? b + 1 : b) * T_ + (T_ - 1)) * F_;
        float snv = snrow[tid];
        const int G = s_G;
        const float r = sh_r;
        const int clsA = 2048 + b, clsB = 2112 + b, clsC = 2176 + b;
        const bool doscan = (b < B_ - 1);
        const bool generic = (G > 32);

        if (!generic) {
            // ---- warp 0: scalar acquisition + group chain ----
            if (wid == 0) {
                int conds; float updidxs, upds_l;
                if (s_scstep == b) {
                    conds = s_tconds; updidxs = s_tidx; upds_l = s_tupl;
                } else if (p_have) {
                    conds = p_conds; updidxs = p_idx; upds_l = p_upl;
                } else {
                    volatile int* rs = &g_sready[b];
                    while (!*rs) { }
                    __threadfence();
                    float4 q = *(const float4*)&g_scal4[b];
                    conds = __float_as_int(q.x); updidxs = q.y; upds_l = q.z;
                }
                // issue next-step readiness probe early (overlaps chain)
                int rn = 0;
                if (b + 1 < B_) rn = *(volatile int*)&g_sready[b + 1];

                bool valid = lane < G;
                int   cls  = valid ? (int)s_gcls[lane] : -1;
                float idxv = valid ? s_gidx[lane] : 0.f;
                float lcv  = valid ? s_glc[lane]  : 0.f;
                u32   gmin = valid ? (u32)s_gmin16[lane] : 0xffffu;
                int   slotv = valid ? (int)s_gslot[lane] : 0xFF;

                float cq = comp_fn(lcv, r);
                float c = 0.f, omc = 0.f, updq_i = 0.f, updq_l = 0.f;
                bool mask = false;
                float i1;
                int wl = 0;
                if (condq) {
                    u32 venc = valid ? fenc(__fadd_rn(cq, 0.0f)) : 0u;
                    u32 vmax = __reduce_max_sync(FULLM, venc);
                    bool tied = valid && (venc == vmax);
                    u32 mng = __reduce_min_sync(FULLM, tied ? gmin : FULLM);
                    u32 wb = __ballot_sync(FULLM, tied && gmin == mng);
                    wl = __ffs(wb) - 1;
                    c = fdec(vmax);
                    float idxmi = __shfl_sync(FULLM, idxv, wl);
                    float lcmi  = __shfl_sync(FULLM, lcv,  wl);
                    omc = __fsub_rn(1.0f, c);
                    updq_i = __fadd_rn(__fmul_rn(idxmi, omc), __fmul_rn(r, c));
                    updq_l = __fadd_rn(__fmul_rn(lcmi,  omc), __fmul_rn(r, c));
                    mask = (cq == c);
                    i1 = mask ? idxv : updq_i;
                } else i1 = idxv;

                bool mm1 = false; float i2;
                if (conds) {
                    float t1 = fdec(__reduce_max_sync(FULLM, valid ? fenc(-i1) : 0u));
                    mm1 = valid && (i1 == t1);
                    i2 = mm1 ? updidxs : i1;
                } else i2 = i1;

                const bool conde = (!condq) && (!conds);
                bool m2 = false; float i3;
                if (conde) {
                    float t2 = fdec(__reduce_max_sync(FULLM, valid ? fenc(-i2) : 0u));
                    m2 = valid && (i2 == t2);
                    i3 = m2 ? r : i2;
                } else i3 = i2;

                const bool uB = conds && mm1;
                const bool uC = conde && m2;
                const bool uA = condq && !mask && !uB;
                const bool upd = uA || uB || uC;

                // leader argmax over i3 (tie: min original row), redux-based
                u32 lenc = valid ? fenc(__fadd_rn(i3, 0.0f)) : 0u;
                u32 lmax = __reduce_max_sync(FULLM, lenc);
                bool ltied = valid && (lenc == lmax);
                u32 lmng = __reduce_min_sync(FULLM, ltied ? gmin : FULLM);
                u32 lb = __ballot_sync(FULLM, ltied && gmin == lmng);
                int ll = __ffs(lb) - 1;

                u32 kb = __ballot_sync(FULLM, valid && !upd);
                int pos = __popc(kb & ((1u << lane) - 1));
                int nk = __popc(kb);
                u32 bA = __ballot_sync(FULLM, valid && uA);
                u32 bB = __ballot_sync(FULLM, valid && uB);
                u32 bC = __ballot_sync(FULLM, valid && uC);
                u32 mnA = __reduce_min_sync(FULLM, (valid && uA) ? gmin : FULLM);
                u32 mnB = __reduce_min_sync(FULLM, (valid && uB) ? gmin : FULLM);
                u32 mnC = __reduce_min_sync(FULLM, (valid && uC) ? gmin : FULLM);
                int idxAe = nk;
                int idxBe = nk + (bA ? 1 : 0);
                int idxCe = nk + (bA ? 1 : 0) + (bB ? 1 : 0);

                if (lane == ll) {
                    s_jt = (!upd) ? pos : (uA ? idxAe : (uB ? idxBe : idxCe));
                    s_imp = fdec(lmax);
                }
                // used-slot mask: kept groups + protected blend-source slot
                u32 ub = (valid && !upd && slotv < NSLOT) ? (1u << slotv) : 0u;
                ub = __reduce_or_sync(FULLM, ub);
                int wlSlot = 0xFF, wlCls = -1;
                if (condq) {
                    int wlUpd = __shfl_sync(FULLM, upd ? 1 : 0, wl);
                    wlSlot = __shfl_sync(FULLM, slotv, wl);
                    wlCls  = __shfl_sync(FULLM, cls, wl);
                    if (wlUpd && wlSlot < NSLOT) ub |= (1u << wlSlot);
                }
                if (valid && !upd) {
                    s_gcls[pos] = (u16)cls; s_gidx[pos] = i3; s_glc[pos] = lcv;
                    s_gmin16[pos] = (u16)gmin; s_gslot[pos] = (u8)slotv;
                }
                // complete next-step quad prefetch
                if (rn) {
                    __threadfence();
                    float4 qn = *(const float4*)&g_scal4[b + 1];
                    p_conds = __float_as_int(qn.x); p_idx = qn.y; p_upl = qn.z;
                }
                p_have = rn;
                __syncwarp();
                if (lane == 0) {
                    s_uvok = rn;
                    int w = nk;
                    if (bA) { s_gcls[w] = (u16)clsA; s_gidx[w] = updq_i; s_glc[w] = updq_l;
                              s_gmin16[w] = (u16)mnA; s_gslot[w] = 0xFF; w++; }
                    if (bB) { s_gcls[w] = (u16)clsB; s_gidx[w] = updidxs; s_glc[w] = upds_l;
                              s_gmin16[w] = (u16)mnB; s_gslot[w] = 0xFF; w++; }
                    if (bC) { s_gcls[w] = (u16)clsC; s_gidx[w] = r; s_glc[w] = r;
                              s_gmin16[w] = (u16)mnC; s_gslot[w] = 0xFF; w++; }
                    s_G = w;
                    u32 freem = (~ub) & ((1u << NSLOT) - 1u);
                    for (int j = 0; j < w; j++) {
                        if (s_gslot[j] == 0xFF) {
                            if (freem) {
                                int f = __ffs(freem) - 1;
                                freem &= ~(1u << f);
                                s_gslot[j] = (u8)f;
                            }
                            s_gfill[j] = 1;
                        } else s_gfill[j] = 0;
                    }
                    if (condq) {
                        s_micls = wlCls;
                        s_misrc = (wlSlot != 0xFF) ? wlSlot : -1;
                        s_c = c;
                    }
                    if (w > 32) {   // overflow: spill to global for generic path
                        for (int j = 0; j < w; j++) {
                            g_bgcls[j] = s_gcls[j]; g_bgidx[j] = s_gidx[j];
                            g_bglc[j]  = s_glc[j];  g_bgmin[j] = s_gmin16[j];
                        }
                    }
                }
            }
            __syncthreads();   // barrier #1

            // ---- fast F-phase ----
            const int uvok = s_uvok;
            if (!uvh) uv = g_upds[(size_t)b * F_ + tid];
            float qv_out = 0.f;
            if (condq) {
                float cF = s_c, omcF = __fsub_rn(1.0f, cF);
                int msrc = s_misrc;
                float srcv = (msrc >= 0) ? s_cache[msrc * F_ + tid]
                                         : cls_ptr(s_micls, memin, states)[tid];
                qv_out = __fadd_rn(__fmul_rn(srcv, omcF), __fmul_rn(sv, cF));
                g_qpool[b][tid] = qv_out;
            }
            const int nG = s_G, jt = s_jt;
            float tval = 0.f;
            int any = 0;
            for (int j = 0; j < nG; j++) {
                int cls2 = s_gcls[j]; int slot = s_gslot[j]; int fill = s_gfill[j];
                float v;
                if (cls2 == clsA)      v = qv_out;
                else if (cls2 == clsB) v = uv;
                else if (cls2 == clsC) v = sv;
                else if (!fill)        v = s_cache[slot * F_ + tid];
                else                   v = cls_ptr(cls2, memin, states)[tid];
                if (fill && slot != 0xFF) s_cache[slot * F_ + tid] = v;
                if (j == jt) tval = v;
                if (doscan) any |= (comp_fn(v, snv) >= EPS_);
            }
            out[(size_t)b * F_ + tid] = tval;
            if (tid == 0) out[(size_t)B_ * F_ + b] = s_imp;
            float uvn = 0.f;
            if (doscan && uvok) uvn = g_upds[(size_t)(b + 1) * F_ + tid];
            if (tid == F_ - 1) sh_r = snv;
            if (doscan) {
                condq = __syncthreads_or(any);
                if (uvok) uv = uvn;
                uvh = uvok;
            }
            sv = snv;
        } else {
            // ======== generic block path (step 0 / fallback), groups in global ====
            if (tid == 0 && s_scstep != b) {
                volatile int* rs = &g_sready[b];
                while (!*rs) { }
                __threadfence();
                float4 q = *(const float4*)&g_scal4[b];
                s_tconds = __float_as_int(q.x); s_tidx = q.y; s_tupl = q.z;
                s_scstep = b;
            }
            __syncthreads();
            const int conds = s_tconds;
            const float updidxs = s_tidx;
            const float upds_l  = s_tupl;
            if (!uvh) uv = g_upds[(size_t)b * F_ + tid];

            const bool v0 = tid < G, v1 = tid + 1024 < G;
            int   cls0 = v0 ? (int)g_bgcls[tid] : -1;
            int   cls1 = v1 ? (int)g_bgcls[tid + 1024] : -1;
            float idx0 = v0 ? g_bgidx[tid] : 0.f, idx1 = v1 ? g_bgidx[tid + 1024] : 0.f;
            float lc0v = v0 ? g_bglc[tid] : 0.f,  lc1v = v1 ? g_bglc[tid + 1024] : 0.f;
            u32   gm0 = v0 ? (u32)g_bgmin[tid] : FULLM;
            u32   gm1 = v1 ? (u32)g_bgmin[tid + 1024] : FULLM;
            float cq0 = comp_fn(lc0v, r), cq1 = comp_fn(lc1v, r);
            float c = 0.f, omc = 0.f, updq_i = 0.f, updq_l = 0.f;
            bool mask0 = false, mask1 = false;
            float i1a, i1b;
            if (condq) {
                u64 p0 = v0 ? pack_gm(fenc(__fadd_rn(cq0, 0.0f)), gm0) : 0ull;
                u64 p1 = v1 ? pack_gm(fenc(__fadd_rn(cq1, 0.0f)), gm1) : 0ull;
                u64 v = max(p0, p1);
                #pragma unroll
                for (int o = 16; o; o >>= 1) v = max(v, __shfl_xor_sync(FULLM, v, o));
                if (lane == 0) s_r64[wid] = v;
                __syncthreads();
                if (wid == 0) {
                    u64 p = s_r64[lane];
                    #pragma unroll
                    for (int o = 16; o; o >>= 1) p = max(p, __shfl_xor_sync(FULLM, p, o));
                    if (lane == 0) s_r64[32] = p;
                }
                __syncthreads();
                u64 pk = s_r64[32];
                __syncthreads();
                c = fdec((u32)(pk >> 32));
                u32 wmin = 0xffffffffu - (u32)pk;
                if (v0 && gm0 == wmin) { s_clsmiS = cls0; s_idxmi = idx0; s_lcmi = lc0v; }
                if (v1 && gm1 == wmin) { s_clsmiS = cls1; s_idxmi = idx1; s_lcmi = lc1v; }
                if (tid == 0) s_c = c;
                __syncthreads();
                omc = __fsub_rn(1.0f, c);
                updq_i = __fadd_rn(__fmul_rn(s_idxmi, omc), __fmul_rn(r, c));
                updq_l = __fadd_rn(__fmul_rn(s_lcmi,  omc), __fmul_rn(r, c));
                mask0 = (cq0 == c); mask1 = (cq1 == c);
                i1a = mask0 ? idx0 : updq_i;
                i1b = mask1 ? idx1 : updq_i;
            } else { i1a = idx0; i1b = idx1; }

            bool mm1a = false, mm1b = false;
            float i2a, i2b;
            if (conds) {
                u32 tv = max(v0 ? fenc(-i1a) : 0u, v1 ? fenc(-i1b) : 0u);
                u32 wm = __reduce_max_sync(FULLM, tv);
                if (lane == 0) s_ru[wid] = wm;
                __syncthreads();
                if (wid == 0) { u32 g = __reduce_max_sync(FULLM, s_ru[lane]); if (lane == 0) s_ru[32] = g; }
                __syncthreads();
                float t1 = fdec(s_ru[32]);
                __syncthreads();
                mm1a = v0 && (i1a == t1); mm1b = v1 && (i1b == t1);
                i2a = mm1a ? updidxs : i1a;
                i2b = mm1b ? updidxs : i1b;
            } else { i2a = i1a; i2b = i1b; }

            const bool conde = (!condq) && (!conds);
            bool m2a = false, m2b = false;
            float i3a, i3b;
            if (conde) {
                u32 tv = max(v0 ? fenc(-i2a) : 0u, v1 ? fenc(-i2b) : 0u);
                u32 wm = __reduce_max_sync(FULLM, tv);
                if (lane == 0) s_ru[wid] = wm;
                __syncthreads();
                if (wid == 0) { u32 g = __reduce_max_sync(FULLM, s_ru[lane]); if (lane == 0) s_ru[32] = g; }
                __syncthreads();
                float t2 = fdec(s_ru[32]);
                __syncthreads();
                m2a = v0 && (i2a == t2); m2b = v1 && (i2b == t2);
                i3a = m2a ? r : i2a;
                i3b = m2b ? r : i2b;
            } else { i3a = i2a; i3b = i2b; }

            const bool uB0 = conds && mm1a, uB1 = conds && mm1b;
            const bool uC0 = conde && m2a,  uC1 = conde && m2b;
            const bool uA0 = condq && !mask0 && !uB0, uA1 = condq && !mask1 && !uB1;
            const bool up0 = uA0 || uB0 || uC0, up1 = uA1 || uB1 || uC1;
            int nc0 = cls0, nc1 = cls1;
            if (uA0) nc0 = clsA; if (uB0) nc0 = clsB; if (uC0) nc0 = clsC;
            if (uA1) nc1 = clsA; if (uB1) nc1 = clsB; if (uC1) nc1 = clsC;

            {   // leader
                u64 p0 = v0 ? pack_gm(fenc(__fadd_rn(i3a, 0.0f)), gm0) : 0ull;
                u64 p1 = v1 ? pack_gm(fenc(__fadd_rn(i3b, 0.0f)), gm1) : 0ull;
                u64 v = max(p0, p1);
                #pragma unroll
                for (int o = 16; o; o >>= 1) v = max(v, __shfl_xor_sync(FULLM, v, o));
                if (lane == 0) s_r64[wid] = v;
                __syncthreads();
                if (wid == 0) {
                    u64 p = s_r64[lane];
                    #pragma unroll
                    for (int o = 16; o; o >>= 1) p = max(p, __shfl_xor_sync(FULLM, p, o));
                    if (lane == 0) s_r64[32] = p;
                }
                __syncthreads();
                u64 pl = s_r64[32];
                u32 wmin = 0xffffffffu - (u32)pl;
                if (v0 && gm0 == wmin) s_tcls = nc0;
                if (v1 && gm1 == wmin) s_tcls = nc1;
                if (tid == 0) { s_imp = fdec((u32)(pl >> 32)); s_cnt = 0; }
                __syncthreads();
            }
            u32 mnA = FULLM, mnB = FULLM, mnC = FULLM;
            {
                u32 a = min((v0 && uA0) ? gm0 : FULLM, (v1 && uA1) ? gm1 : FULLM);
                u32 bm = min((v0 && uB0) ? gm0 : FULLM, (v1 && uB1) ? gm1 : FULLM);
                u32 cm = min((v0 && uC0) ? gm0 : FULLM, (v1 && uC1) ? gm1 : FULLM);
                u32 wa = __reduce_min_sync(FULLM, a);
                u32 wb2 = __reduce_min_sync(FULLM, bm);
                u32 wc = __reduce_min_sync(FULLM, cm);
                if (lane == 0) { s_ru[wid] = wa; }
                __syncthreads();
                if (wid == 0) { u32 g = __reduce_min_sync(FULLM, s_ru[lane]); if (lane == 0) s_ru[32] = g; }
                __syncthreads();
                mnA = s_ru[32]; __syncthreads();
                if (lane == 0) { s_ru[wid] = wb2; }
                __syncthreads();
                if (wid == 0) { u32 g = __reduce_min_sync(FULLM, s_ru[lane]); if (lane == 0) s_ru[32] = g; }
                __syncthreads();
                mnB = s_ru[32]; __syncthreads();
                if (lane == 0) { s_ru[wid] = wc; }
                __syncthreads();
                if (wid == 0) { u32 g = __reduce_min_sync(FULLM, s_ru[lane]); if (lane == 0) s_ru[32] = g; }
                __syncthreads();
                mnC = s_ru[32]; __syncthreads();
            }
            // compaction via aggregated atomics into global arrays
            {
                bool k0 = v0 && !up0;
                u32 bk = __ballot_sync(FULLM, k0);
                if (bk) {
                    int ldr = __ffs(bk) - 1;
                    int base = 0;
                    if (lane == ldr) base = atomicAdd(&s_cnt, __popc(bk));
                    base = __shfl_sync(FULLM, base, ldr);
                    if (k0) {
                        int p = base + __popc(bk & ((1u << lane) - 1));
                        g_bgcls[p] = (u16)cls0; g_bgidx[p] = idx0;
                        g_bglc[p] = lc0v; g_bgmin[p] = (u16)gm0;
                    }
                }
                bool k1 = v1 && !up1;
                bk = __ballot_sync(FULLM, k1);
                if (bk) {
                    int ldr = __ffs(bk) - 1;
                    int base = 0;
                    if (lane == ldr) base = atomicAdd(&s_cnt, __popc(bk));
                    base = __shfl_sync(FULLM, base, ldr);
                    if (k1) {
                        int p = base + __popc(bk & ((1u << lane) - 1));
                        g_bgcls[p] = (u16)cls1; g_bgidx[p] = idx1;
                        g_bglc[p] = lc1v; g_bgmin[p] = (u16)gm1;
                    }
                }
            }
            __syncthreads();
            if (tid == 0) {
                int w = s_cnt;
                if (mnA != FULLM) { g_bgcls[w] = (u16)clsA; g_bgidx[w] = updq_i;
                                    g_bglc[w] = updq_l; g_bgmin[w] = (u16)mnA; w++; }
                if (mnB != FULLM) { g_bgcls[w] = (u16)clsB; g_bgidx[w] = updidxs;
                                    g_bglc[w] = upds_l; g_bgmin[w] = (u16)mnB; w++; }
                if (mnC != FULLM) { g_bgcls[w] = (u16)clsC; g_bgidx[w] = r;
                                    g_bglc[w] = r; g_bgmin[w] = (u16)mnC; w++; }
                s_G = w;
                if (b + 1 < B_) {
                    volatile int* rs = &g_sready[b + 1];
                    while (!*rs) { }
                    __threadfence();
                    float4 q = *(const float4*)&g_scal4[b + 1];
                    s_tconds = __float_as_int(q.x); s_tidx = q.y; s_tupl = q.z;
                    s_scstep = b + 1;
                }
            }
            __syncthreads();
            // copy compacted groups to smem if small (cache starts empty)
            const int wNew = s_G;
            if (wNew <= 32 && tid < wNew) {
                s_gcls[tid] = g_bgcls[tid]; s_gidx[tid] = g_bgidx[tid];
                s_glc[tid] = g_bglc[tid]; s_gmin16[tid] = g_bgmin[tid];
                s_gslot[tid] = 0xFF; s_gfill[tid] = 0;
            }

            // ---- slow F-phase ----
            float qv_out = 0.f;
            if (condq) {
                float cF = s_c, omcF = __fsub_rn(1.0f, cF);
                float srcv = cls_ptr(s_clsmiS, memin, states)[tid];
                qv_out = __fadd_rn(__fmul_rn(srcv, omcF), __fmul_rn(sv, cF));
                g_qpool[b][tid] = qv_out;
            }
            {
                int tcls = s_tcls;
                float tval;
                if (tcls == clsA)      tval = qv_out;
                else if (tcls == clsB) tval = uv;
                else if (tcls == clsC) tval = sv;
                else tval = cls_ptr(tcls, memin, states)[tid];
                out[(size_t)b * F_ + tid] = tval;
            }
            if (tid == 0) out[(size_t)B_ * F_ + b] = s_imp;
            float uvn = doscan ? g_upds[(size_t)(b + 1) * F_ + tid] : 0.f;
            int any = 0;
            if (doscan) {
                for (int j = 0; j < wNew; j++) {
                    int cls2 = g_bgcls[j];
                    float v;
                    if (cls2 == clsA)      v = qv_out;
                    else if (cls2 == clsB) v = uv;
                    else if (cls2 == clsC) v = sv;
                    else v = cls_ptr(cls2, memin, states)[tid];
                    any |= (comp_fn(v, snv) >= EPS_);
                }
            }
            if (tid == F_ - 1) sh_r = snv;
            if (doscan) {
                condq = __syncthreads_or(any);
                uv = uvn;
                uvh = 1;
            }
            sv = snv;
        }
    }
}

// ---------------- launch ----------------
extern "C" void kernel_launch(void* const* d_in, const int* in_sizes, int n_in,
                              void* d_out, int out_size) {
    const float* states = (const float*)d_in[0];   // (64,128,1024)
    const float* mr     = (const float*)d_in[1];   // (64,512,1024)
    const float* memin  = (const float*)d_in[2];   // (2048,1024)
    const float* index  = (const float*)d_in[3];   // (2048,1)
    float* out = (float*)d_out;                    // targets(64*1024) ++ importances(64)

    k_reset<<<1, 128>>>();
    mega<<<NB, NT>>>(states, mr, memin, index, out);
}

// round 12
// speedup vs baseline: 1.2407x; 1.2407x over previous
#include <cuda_runtime.h>
#include <cstdint>

#define B_ 64
#define T_ 128
#define F_ 1024
#define S_ 512
#define M_ 2048
#define EPS_ 0.45f
#define NB 128
#define NT 1024
#define NSLOT 10
#define FULLM 0xffffffffu

typedef unsigned long long u64;
typedef unsigned u32;
typedef unsigned short u16;
typedef unsigned char u8;

// ---------------- device scratch (static, no allocation) ----------------
__device__ float g_qpool[B_][F_];      // materialized upd_mem_q per step
__device__ float g_upds[B_ * F_];      // precomputed upd_mem_s per step
__device__ float g_updidxs[B_];        // precomputed upd_idx_s per step
__device__ float g_lc0[M_];            // memin[:, -1]
__device__ int   g_flags[B_];          // per-step cond_s
__device__ int   g_flagq0;             // step-0 cond_q
__device__ int   g_scnt[B_];           // per-step chunk arrival count
__device__ int   g_sready[B_];         // step data ready (release flag)
__device__ float4 g_scal4[B_];         // packed {conds, updidxs, upds_l, 0}
__device__ int   g_ticket;             // worker chunk dispenser
__device__ int   g_readyQ;             // memin scan done count
// generic-path (big-G) group arrays
__device__ float g_bgidx[M_];
__device__ float g_bglc[M_];
__device__ u16   g_bgcls[M_];
__device__ u16   g_bgmin[M_];

// ---------------- helpers ----------------
__device__ __forceinline__ float comp_fn(float x, float s) {
    float d  = __fsub_rn(x, s);
    float t  = __fadd_rn(__fmul_rn(0.2f, d), 0.5f);
    float hs = fminf(fmaxf(t, 0.0f), 1.0f);
    return __fsub_rn(0.5f, hs);
}
__device__ __forceinline__ u32 fenc(float x) {
    u32 u = __float_as_uint(x);
    return (u & 0x80000000u) ? ~u : (u | 0x80000000u);
}
__device__ __forceinline__ float fdec(u32 u) {
    u32 v = (u & 0x80000000u) ? (u & 0x7FFFFFFFu) : ~u;
    return __uint_as_float(v);
}
__device__ __forceinline__ u64 pack_gm(u32 venc, u32 gmin) {
    return ((u64)venc << 32) | (u64)(0xffffffffu - gmin);
}
__device__ __forceinline__ const float* cls_ptr(int id,
        const float* __restrict__ memin, const float* __restrict__ states) {
    if (id < 2048) return memin + (size_t)id * F_;
    if (id < 2112) return g_qpool[id - 2048];
    if (id < 2176) return g_upds + (size_t)(id - 2112) * F_;
    return states + ((size_t)(id - 2176) * T_ + (T_ - 1)) * F_;
}

__global__ void k_reset() {
    int t = threadIdx.x;
    if (t < B_) { g_flags[t] = 0; g_scnt[t] = 0; g_sready[t] = 0; }
    if (t == 0) { g_ticket = 0; g_readyQ = 0; g_flagq0 = 0; }
}

// ---------------- persistent kernel ----------------
__global__ void __launch_bounds__(NT, 1) mega(
    const float* __restrict__ states, const float* __restrict__ mr,
    const float* __restrict__ memin, const float* __restrict__ index,
    float* __restrict__ out)
{
    __shared__ float s_cache[NSLOT * F_];       // 40KB class-vector cache
    __shared__ float s_gidx[64], s_glc[64];     // small group arrays (warp path)
    __shared__ u16 s_gcls[64], s_gmin16[64];
    __shared__ u8  s_gslot[64], s_gfill[64];
    __shared__ float4 s_qring[8];               // prefetched scalar quads
    __shared__ u64 s_r64[33];
    __shared__ u32 s_ru[33];
    __shared__ int s_G, s_jt, s_misrc, s_micls, s_cnt, s_tcls, s_tk, s_clsmiS;
    __shared__ float sh_r, s_c, s_imp, s_idxmi, s_lcmi;

    const int bid = blockIdx.x, tid = threadIdx.x;
    const int lane = tid & 31, wid = tid >> 5;

    // ================= WORKERS (bid 1..127) =================
    if (bid != 0) {
        {   // memin scan share + lc0 + flagq0
            const float* s0 = states + (size_t)(T_ - 1) * F_;
            float s0v = s0[tid];
            int start = (bid - 1) * 17, end = min(start + 17, M_);
            int any = 0;
            for (int row = start; row < end; row++) {
                float v = memin[(size_t)row * F_ + tid];
                if (tid == F_ - 1) g_lc0[row] = v;
                any |= (comp_fn(v, s0v) >= EPS_);
            }
            int anyb = __syncthreads_or(any);
            __threadfence();
            __syncthreads();
            if (tid == 0) {
                if (anyb) atomicOr(&g_flagq0, 1);
                __threadfence();
                atomicAdd(&g_readyQ, 1);
            }
        }
        // ticket loop: 512 chunks = 64 steps x 8 col-chunks, in step order
        float* scrA = s_cache; float* scrB = s_cache + NT;
        while (true) {
            if (tid == 0) s_tk = atomicAdd(&g_ticket, 1);
            __syncthreads();
            int t = s_tk;
            if (t >= 512) break;
            const int b = t >> 3, ch = t & 7;
            const int col = ch * 128 + (tid & 127);
            const int rg = tid >> 7;   // 8 row groups of 64 rows
            const float* srow = states + ((size_t)b * T_ + (T_ - 1)) * F_;
            const float sf = srow[col];
            const float* mrb = mr + (size_t)b * S_ * F_;
            float mx = -3.402823466e38f, ma = 0.0f; int any2 = 0;
            #pragma unroll 8
            for (int ri = rg; ri < S_; ri += 8) {
                float v  = mrb[(size_t)ri * F_ + col];
                float cp = comp_fn(v, sf);
                any2 |= (cp >= EPS_);
                ma = fmaxf(ma, fabsf(cp));
                mx = fmaxf(mx, v);
            }
            scrA[tid] = mx; scrB[tid] = ma;
            int anyc = __syncthreads_or(any2);
            if (tid < 128) {
                float amx = scrA[tid], ama = scrB[tid];
                #pragma unroll
                for (int g = 1; g < 8; g++) {
                    amx = fmaxf(amx, scrA[g * 128 + tid]);
                    ama = fmaxf(ama, scrB[g * 128 + tid]);
                }
                int cc = ch * 128 + tid;
                float cs = __fmul_rn(sqrtf((float)S_), ama);
                g_upds[(size_t)b * F_ + cc] =
                    __fadd_rn(__fmul_rn(amx, cs), __fmul_rn(sf, __fsub_rn(1.0f, cs)));
                if (cc == F_ - 1) {
                    float mr0 = mrb[F_ - 1];   // mr[0, -1]
                    g_updidxs[b] = __fadd_rn(__fmul_rn(mr0, cs),
                                             __fmul_rn(sf, __fsub_rn(1.0f, cs)));
                }
            }
            __threadfence();
            __syncthreads();
            if (tid == 0) {
                if (anyc) atomicOr(&g_flags[b], 1);
                __threadfence();
                int done = atomicAdd(&g_scnt[b], 1);
                if (done == 7) {
                    __threadfence();
                    float4 q;
                    q.x = __int_as_float(*(volatile int*)&g_flags[b]);
                    q.y = *(volatile float*)&g_updidxs[b];
                    q.z = *(volatile float*)&g_upds[(size_t)b * F_ + F_ - 1];
                    q.w = 0.0f;
                    g_scal4[b] = q;
                    __threadfence();
                    atomicExch(&g_sready[b], 1);
                }
            }
            __syncthreads();
        }
        return;
    }

    // ================= CONSUMER (block 0) =================
    int pf = 0;   // prefetch cursor (meaningful only in warp 1 lane 0)
    if (tid == 0) {
        volatile int* rq = &g_readyQ;
        while (*rq < NB - 1) { }
        __threadfence();
        s_G = M_;
    }
    if (wid == 1 && lane == 0) {
        volatile int* rs = &g_sready[0];
        while (!*rs) { }
        __threadfence();
        s_qring[0] = *(const float4*)&g_scal4[0];
        pf = 1;
        while (pf < 8) {                     // opportunistic prologue lead
            if (!*(volatile int*)&g_sready[pf]) break;
            __threadfence();
            s_qring[pf & 7] = *(const float4*)&g_scal4[pf];
            pf++;
        }
    }
    __syncthreads();
    int condq = g_flagq0;
    float uv = g_upds[tid];                  // safe: sready[0] fenced + barrier
    #pragma unroll
    for (int k = 0; k < 2; k++) {
        int m = tid + k * 1024;
        g_bgidx[m] = index[m];
        g_bglc[m]  = g_lc0[m];
        g_bgcls[m] = (u16)m;
        g_bgmin[m] = (u16)m;
    }
    float sv = states[(size_t)(T_ - 1) * F_ + tid];
    if (tid == F_ - 1) sh_r = sv;
    __syncthreads();

    for (int b = 0; b < B_; b++) {
        const float* snrow = states + ((size_t)((b < B_ - 1) ? b + 1 : b) * T_ + (T_ - 1)) * F_;
        float snv = snrow[tid];
        const int G = s_G;
        const float r = sh_r;
        const int clsA = 2048 + b, clsB = 2112 + b, clsC = 2176 + b;
        const bool doscan = (b < B_ - 1);
        const bool generic = (G > 32);

        // ---- warp 1 lane 0: ring prefetch (parallel with warp 0 chain) ----
        // invariant established here for step b: pf >= min(B_, b+2) before barrier #1,
        // which guarantees g_sready[b+1] observed+fenced before any g_upds[b+1] read.
        if (wid == 1 && lane == 0) {
            const int need = min(B_, b + 2);
            while (pf < need) {
                if (*(volatile int*)&g_sready[pf]) {
                    __threadfence();
                    s_qring[pf & 7] = *(const float4*)&g_scal4[pf];
                    pf++;
                }
            }
            const int cap = min(B_, b + 8);
            while (pf < cap) {               // extend lead, non-blocking
                if (!*(volatile int*)&g_sready[pf]) break;
                __threadfence();
                s_qring[pf & 7] = *(const float4*)&g_scal4[pf];
                pf++;
            }
        }

        // per-step scalars from ring (slot b&7 written at step <= b-1, then barrier)
        const float4 q = s_qring[b & 7];
        const int   conds   = __float_as_int(q.x);
        const float updidxs = q.y;
        const float upds_l  = q.z;

        if (!generic) {
            // ---- warp 0: group chain ----
            if (wid == 0) {
                bool valid = lane < G;
                int   cls  = valid ? (int)s_gcls[lane] : -1;
                float idxv = valid ? s_gidx[lane] : 0.f;
                float lcv  = valid ? s_glc[lane]  : 0.f;
                u32   gmin = valid ? (u32)s_gmin16[lane] : 0xffffu;
                int   slotv = valid ? (int)s_gslot[lane] : 0xFF;

                float cq = comp_fn(lcv, r);
                float c = 0.f, omc = 0.f, updq_i = 0.f, updq_l = 0.f;
                bool mask = false;
                float i1;
                int wl = 0;
                if (condq) {
                    u32 venc = valid ? fenc(__fadd_rn(cq, 0.0f)) : 0u;
                    u32 vmax = __reduce_max_sync(FULLM, venc);
                    bool tied = valid && (venc == vmax);
                    u32 mng = __reduce_min_sync(FULLM, tied ? gmin : FULLM);
                    u32 wb = __ballot_sync(FULLM, tied && gmin == mng);
                    wl = __ffs(wb) - 1;
                    c = fdec(vmax);
                    float idxmi = __shfl_sync(FULLM, idxv, wl);
                    float lcmi  = __shfl_sync(FULLM, lcv,  wl);
                    omc = __fsub_rn(1.0f, c);
                    updq_i = __fadd_rn(__fmul_rn(idxmi, omc), __fmul_rn(r, c));
                    updq_l = __fadd_rn(__fmul_rn(lcmi,  omc), __fmul_rn(r, c));
                    mask = (cq == c);
                    i1 = mask ? idxv : updq_i;
                } else i1 = idxv;

                bool mm1 = false; float i2;
                if (conds) {
                    float t1 = fdec(__reduce_max_sync(FULLM, valid ? fenc(-i1) : 0u));
                    mm1 = valid && (i1 == t1);
                    i2 = mm1 ? updidxs : i1;
                } else i2 = i1;

                const bool conde = (!condq) && (!conds);
                bool m2 = false; float i3;
                if (conde) {
                    float t2 = fdec(__reduce_max_sync(FULLM, valid ? fenc(-i2) : 0u));
                    m2 = valid && (i2 == t2);
                    i3 = m2 ? r : i2;
                } else i3 = i2;

                const bool uB = conds && mm1;
                const bool uC = conde && m2;
                const bool uA = condq && !mask && !uB;
                const bool upd = uA || uB || uC;

                // leader argmax over i3 (tie: min original row), redux-based
                u32 lenc = valid ? fenc(__fadd_rn(i3, 0.0f)) : 0u;
                u32 lmax = __reduce_max_sync(FULLM, lenc);
                bool ltied = valid && (lenc == lmax);
                u32 lmng = __reduce_min_sync(FULLM, ltied ? gmin : FULLM);
                u32 lb = __ballot_sync(FULLM, ltied && gmin == lmng);
                int ll = __ffs(lb) - 1;

                u32 kb = __ballot_sync(FULLM, valid && !upd);
                int pos = __popc(kb & ((1u << lane) - 1));
                int nk = __popc(kb);
                u32 bA = __ballot_sync(FULLM, valid && uA);
                u32 bB = __ballot_sync(FULLM, valid && uB);
                u32 bC = __ballot_sync(FULLM, valid && uC);
                u32 mnA = __reduce_min_sync(FULLM, (valid && uA) ? gmin : FULLM);
                u32 mnB = __reduce_min_sync(FULLM, (valid && uB) ? gmin : FULLM);
                u32 mnC = __reduce_min_sync(FULLM, (valid && uC) ? gmin : FULLM);
                int idxAe = nk;
                int idxBe = nk + (bA ? 1 : 0);
                int idxCe = nk + (bA ? 1 : 0) + (bB ? 1 : 0);

                if (lane == ll) {
                    s_jt = (!upd) ? pos : (uA ? idxAe : (uB ? idxBe : idxCe));
                    s_imp = fdec(lmax);
                }
                // used-slot mask: kept groups + protected blend-source slot
                u32 ub = (valid && !upd && slotv < NSLOT) ? (1u << slotv) : 0u;
                ub = __reduce_or_sync(FULLM, ub);
                int wlSlot = 0xFF, wlCls = -1;
                if (condq) {
                    int wlUpd = __shfl_sync(FULLM, upd ? 1 : 0, wl);
                    wlSlot = __shfl_sync(FULLM, slotv, wl);
                    wlCls  = __shfl_sync(FULLM, cls, wl);
                    if (wlUpd && wlSlot < NSLOT) ub |= (1u << wlSlot);
                }
                if (valid && !upd) {
                    s_gcls[pos] = (u16)cls; s_gidx[pos] = i3; s_glc[pos] = lcv;
                    s_gmin16[pos] = (u16)gmin; s_gslot[pos] = (u8)slotv;
                }
                __syncwarp();
                if (lane == 0) {
                    int w = nk;
                    if (bA) { s_gcls[w] = (u16)clsA; s_gidx[w] = updq_i; s_glc[w] = updq_l;
                              s_gmin16[w] = (u16)mnA; s_gslot[w] = 0xFF; w++; }
                    if (bB) { s_gcls[w] = (u16)clsB; s_gidx[w] = updidxs; s_glc[w] = upds_l;
                              s_gmin16[w] = (u16)mnB; s_gslot[w] = 0xFF; w++; }
                    if (bC) { s_gcls[w] = (u16)clsC; s_gidx[w] = r; s_glc[w] = r;
                              s_gmin16[w] = (u16)mnC; s_gslot[w] = 0xFF; w++; }
                    s_G = w;
                    u32 freem = (~ub) & ((1u << NSLOT) - 1u);
                    for (int j = 0; j < w; j++) {
                        if (s_gslot[j] == 0xFF) {
                            if (freem) {
                                int f = __ffs(freem) - 1;
                                freem &= ~(1u << f);
                                s_gslot[j] = (u8)f;
                            }
                            s_gfill[j] = 1;
                        } else s_gfill[j] = 0;
                    }
                    if (condq) {
                        s_micls = wlCls;
                        s_misrc = (wlSlot != 0xFF) ? wlSlot : -1;
                        s_c = c;
                    }
                    if (w > 32) {   // overflow: spill to global for generic path
                        for (int j = 0; j < w; j++) {
                            g_bgcls[j] = s_gcls[j]; g_bgidx[j] = s_gidx[j];
                            g_bglc[j]  = s_glc[j];  g_bgmin[j] = s_gmin16[j];
                        }
                    }
                }
            }
            __syncthreads();   // barrier #1

            // ---- fast F-phase ----
            float qv_out = 0.f;
            if (condq) {
                float cF = s_c, omcF = __fsub_rn(1.0f, cF);
                int msrc = s_misrc;
                float srcv = (msrc >= 0) ? s_cache[msrc * F_ + tid]
                                         : cls_ptr(s_micls, memin, states)[tid];
                qv_out = __fadd_rn(__fmul_rn(srcv, omcF), __fmul_rn(sv, cF));
                g_qpool[b][tid] = qv_out;
            }
            const int nG = s_G, jt = s_jt;
            float tval = 0.f;
            int any = 0;
            for (int j = 0; j < nG; j++) {
                int cls2 = s_gcls[j]; int slot = s_gslot[j]; int fill = s_gfill[j];
                float v;
                if (cls2 == clsA)      v = qv_out;
                else if (cls2 == clsB) v = uv;
                else if (cls2 == clsC) v = sv;
                else if (!fill)        v = s_cache[slot * F_ + tid];
                else                   v = cls_ptr(cls2, memin, states)[tid];
                if (fill && slot != 0xFF) s_cache[slot * F_ + tid] = v;
                if (j == jt) tval = v;
                if (doscan) any |= (comp_fn(v, snv) >= EPS_);
            }
            out[(size_t)b * F_ + tid] = tval;
            if (tid == 0) out[(size_t)B_ * F_ + b] = s_imp;
            // safe: pf>=b+2 ensured before barrier #1 => g_upds[b+1] published
            float uvn = doscan ? g_upds[(size_t)(b + 1) * F_ + tid] : 0.f;
            if (tid == F_ - 1) sh_r = snv;
            if (doscan) {
                condq = __syncthreads_or(any);
                uv = uvn;
            }
            sv = snv;
        } else {
            // ======== generic block path (step 0 / fallback), groups in global ====
            const bool v0 = tid < G, v1 = tid + 1024 < G;
            int   cls0 = v0 ? (int)g_bgcls[tid] : -1;
            int   cls1 = v1 ? (int)g_bgcls[tid + 1024] : -1;
            float idx0 = v0 ? g_bgidx[tid] : 0.f, idx1 = v1 ? g_bgidx[tid + 1024] : 0.f;
            float lc0v = v0 ? g_bglc[tid] : 0.f,  lc1v = v1 ? g_bglc[tid + 1024] : 0.f;
            u32   gm0 = v0 ? (u32)g_bgmin[tid] : FULLM;
            u32   gm1 = v1 ? (u32)g_bgmin[tid + 1024] : FULLM;
            float cq0 = comp_fn(lc0v, r), cq1 = comp_fn(lc1v, r);
            float c = 0.f, omc = 0.f, updq_i = 0.f, updq_l = 0.f;
            bool mask0 = false, mask1 = false;
            float i1a, i1b;
            if (condq) {
                u64 p0 = v0 ? pack_gm(fenc(__fadd_rn(cq0, 0.0f)), gm0) : 0ull;
                u64 p1 = v1 ? pack_gm(fenc(__fadd_rn(cq1, 0.0f)), gm1) : 0ull;
                u64 v = max(p0, p1);
                #pragma unroll
                for (int o = 16; o; o >>= 1) v = max(v, __shfl_xor_sync(FULLM, v, o));
                if (lane == 0) s_r64[wid] = v;
                __syncthreads();
                if (wid == 0) {
                    u64 p = s_r64[lane];
                    #pragma unroll
                    for (int o = 16; o; o >>= 1) p = max(p, __shfl_xor_sync(FULLM, p, o));
                    if (lane == 0) s_r64[32] = p;
                }
                __syncthreads();
                u64 pk = s_r64[32];
                __syncthreads();
                c = fdec((u32)(pk >> 32));
                u32 wmin = 0xffffffffu - (u32)pk;
                if (v0 && gm0 == wmin) { s_clsmiS = cls0; s_idxmi = idx0; s_lcmi = lc0v; }
                if (v1 && gm1 == wmin) { s_clsmiS = cls1; s_idxmi = idx1; s_lcmi = lc1v; }
                if (tid == 0) s_c = c;
                __syncthreads();
                omc = __fsub_rn(1.0f, c);
                updq_i = __fadd_rn(__fmul_rn(s_idxmi, omc), __fmul_rn(r, c));
                updq_l = __fadd_rn(__fmul_rn(s_lcmi,  omc), __fmul_rn(r, c));
                mask0 = (cq0 == c); mask1 = (cq1 == c);
                i1a = mask0 ? idx0 : updq_i;
                i1b = mask1 ? idx1 : updq_i;
            } else { i1a = idx0; i1b = idx1; }

            bool mm1a = false, mm1b = false;
            float i2a, i2b;
            if (conds) {
                u32 tv = max(v0 ? fenc(-i1a) : 0u, v1 ? fenc(-i1b) : 0u);
                u32 wm = __reduce_max_sync(FULLM, tv);
                if (lane == 0) s_ru[wid] = wm;
                __syncthreads();
                if (wid == 0) { u32 g = __reduce_max_sync(FULLM, s_ru[lane]); if (lane == 0) s_ru[32] = g; }
                __syncthreads();
                float t1 = fdec(s_ru[32]);
                __syncthreads();
                mm1a = v0 && (i1a == t1); mm1b = v1 && (i1b == t1);
                i2a = mm1a ? updidxs : i1a;
                i2b = mm1b ? updidxs : i1b;
            } else { i2a = i1a; i2b = i1b; }

            const bool conde = (!condq) && (!conds);
            bool m2a = false, m2b = false;
            float i3a, i3b;
            if (conde) {
                u32 tv = max(v0 ? fenc(-i2a) : 0u, v1 ? fenc(-i2b) : 0u);
                u32 wm = __reduce_max_sync(FULLM, tv);
                if (lane == 0) s_ru[wid] = wm;
                __syncthreads();
                if (wid == 0) { u32 g = __reduce_max_sync(FULLM, s_ru[lane]); if (lane == 0) s_ru[32] = g; }
                __syncthreads();
                float t2 = fdec(s_ru[32]);
                __syncthreads();
                m2a = v0 && (i2a == t2); m2b = v1 && (i2b == t2);
                i3a = m2a ? r : i2a;
                i3b = m2b ? r : i2b;
            } else { i3a = i2a; i3b = i2b; }

            const bool uB0 = conds && mm1a, uB1 = conds && mm1b;
            const bool uC0 = conde && m2a,  uC1 = conde && m2b;
            const bool uA0 = condq && !mask0 && !uB0, uA1 = condq && !mask1 && !uB1;
            const bool up0 = uA0 || uB0 || uC0, up1 = uA1 || uB1 || uC1;
            int nc0 = cls0, nc1 = cls1;
            if (uA0) nc0 = clsA; if (uB0) nc0 = clsB; if (uC0) nc0 = clsC;
            if (uA1) nc1 = clsA; if (uB1) nc1 = clsB; if (uC1) nc1 = clsC;

            {   // leader
                u64 p0 = v0 ? pack_gm(fenc(__fadd_rn(i3a, 0.0f)), gm0) : 0ull;
                u64 p1 = v1 ? pack_gm(fenc(__fadd_rn(i3b, 0.0f)), gm1) : 0ull;
                u64 v = max(p0, p1);
                #pragma unroll
                for (int o = 16; o; o >>= 1) v = max(v, __shfl_xor_sync(FULLM, v, o));
                if (lane == 0) s_r64[wid] = v;
                __syncthreads();
                if (wid == 0) {
                    u64 p = s_r64[lane];
                    #pragma unroll
                    for (int o = 16; o; o >>= 1) p = max(p, __shfl_xor_sync(FULLM, p, o));
                    if (lane == 0) s_r64[32] = p;
                }
                __syncthreads();
                u64 pl = s_r64[32];
                u32 wmin = 0xffffffffu - (u32)pl;
                if (v0 && gm0 == wmin) s_tcls = nc0;
                if (v1 && gm1 == wmin) s_tcls = nc1;
                if (tid == 0) { s_imp = fdec((u32)(pl >> 32)); s_cnt = 0; }
                __syncthreads();
            }
            u32 mnA = FULLM, mnB = FULLM, mnC = FULLM;
            {
                u32 a = min((v0 && uA0) ? gm0 : FULLM, (v1 && uA1) ? gm1 : FULLM);
                u32 bm = min((v0 && uB0) ? gm0 : FULLM, (v1 && uB1) ? gm1 : FULLM);
                u32 cm = min((v0 && uC0) ? gm0 : FULLM, (v1 && uC1) ? gm1 : FULLM);
                u32 wa = __reduce_min_sync(FULLM, a);
                u32 wb2 = __reduce_min_sync(FULLM, bm);
                u32 wc = __reduce_min_sync(FULLM, cm);
                if (lane == 0) { s_ru[wid] = wa; }
                __syncthreads();
                if (wid == 0) { u32 g = __reduce_min_sync(FULLM, s_ru[lane]); if (lane == 0) s_ru[32] = g; }
                __syncthreads();
                mnA = s_ru[32]; __syncthreads();
                if (lane == 0) { s_ru[wid] = wb2; }
                __syncthreads();
                if (wid == 0) { u32 g = __reduce_min_sync(FULLM, s_ru[lane]); if (lane == 0) s_ru[32] = g; }
                __syncthreads();
                mnB = s_ru[32]; __syncthreads();
                if (lane == 0) { s_ru[wid] = wc; }
                __syncthreads();
                if (wid == 0) { u32 g = __reduce_min_sync(FULLM, s_ru[lane]); if (lane == 0) s_ru[32] = g; }
                __syncthreads();
                mnC = s_ru[32]; __syncthreads();
            }
            // compaction via aggregated atomics into global arrays
            {
                bool k0 = v0 && !up0;
                u32 bk = __ballot_sync(FULLM, k0);
                if (bk) {
                    int ldr = __ffs(bk) - 1;
                    int base = 0;
                    if (lane == ldr) base = atomicAdd(&s_cnt, __popc(bk));
                    base = __shfl_sync(FULLM, base, ldr);
                    if (k0) {
                        int p = base + __popc(bk & ((1u << lane) - 1));
                        g_bgcls[p] = (u16)cls0; g_bgidx[p] = i3a;
                        g_bglc[p] = lc0v; g_bgmin[p] = (u16)gm0;
                    }
                }
                bool k1 = v1 && !up1;
                bk = __ballot_sync(FULLM, k1);
                if (bk) {
                    int ldr = __ffs(bk) - 1;
                    int base = 0;
                    if (lane == ldr) base = atomicAdd(&s_cnt, __popc(bk));
                    base = __shfl_sync(FULLM, base, ldr);
                    if (k1) {
                        int p = base + __popc(bk & ((1u << lane) - 1));
                        g_bgcls[p] = (u16)cls1; g_bgidx[p] = i3b;
                        g_bglc[p] = lc1v; g_bgmin[p] = (u16)gm1;
                    }
                }
            }
            __syncthreads();
            if (tid == 0) {
                int w = s_cnt;
                if (mnA != FULLM) { g_bgcls[w] = (u16)clsA; g_bgidx[w] = updq_i;
                                    g_bglc[w] = updq_l; g_bgmin[w] = (u16)mnA; w++; }
                if (mnB != FULLM) { g_bgcls[w] = (u16)clsB; g_bgidx[w] = updidxs;
                                    g_bglc[w] = upds_l; g_bgmin[w] = (u16)mnB; w++; }
                if (mnC != FULLM) { g_bgcls[w] = (u16)clsC; g_bgidx[w] = r;
                                    g_bglc[w] = r; g_bgmin[w] = (u16)mnC; w++; }
                s_G = w;
            }
            __syncthreads();
            // copy compacted groups to smem if small (cache starts empty)
            const int wNew = s_G;
            if (wNew <= 32 && tid < wNew) {
                s_gcls[tid] = g_bgcls[tid]; s_gidx[tid] = g_bgidx[tid];
                s_glc[tid] = g_bglc[tid]; s_gmin16[tid] = g_bgmin[tid];
                s_gslot[tid] = 0xFF; s_gfill[tid] = 0;
            }

            // ---- slow F-phase ----
            float qv_out = 0.f;
            if (condq) {
                float cF = s_c, omcF = __fsub_rn(1.0f, cF);
                float srcv = cls_ptr(s_clsmiS, memin, states)[tid];
                qv_out = __fadd_rn(__fmul_rn(srcv, omcF), __fmul_rn(sv, cF));
                g_qpool[b][tid] = qv_out;
            }
            {
                int tcls = s_tcls;
                float tval;
                if (tcls == clsA)      tval = qv_out;
                else if (tcls == clsB) tval = uv;
                else if (tcls == clsC) tval = sv;
                else tval = cls_ptr(tcls, memin, states)[tid];
                out[(size_t)b * F_ + tid] = tval;
            }
            if (tid == 0) out[(size_t)B_ * F_ + b] = s_imp;
            float uvn = doscan ? g_upds[(size_t)(b + 1) * F_ + tid] : 0.f;
            int any = 0;
            if (doscan) {
                for (int j = 0; j < wNew; j++) {
                    int cls2 = g_bgcls[j];
                    float v;
                    if (cls2 == clsA)      v = qv_out;
                    else if (cls2 == clsB) v = uv;
                    else if (cls2 == clsC) v = sv;
                    else v = cls_ptr(cls2, memin, states)[tid];
                    any |= (comp_fn(v, snv) >= EPS_);
                }
            }
            if (tid == F_ - 1) sh_r = snv;
            if (doscan) {
                condq = __syncthreads_or(any);
                uv = uvn;
            }
            sv = snv;
        }
    }
}

// ---------------- launch ----------------
extern "C" void kernel_launch(void* const* d_in, const int* in_sizes, int n_in,
                              void* d_out, int out_size) {
    const float* states = (const float*)d_in[0];   // (64,128,1024)
    const float* mr     = (const float*)d_in[1];   // (64,512,1024)
    const float* memin  = (const float*)d_in[2];   // (2048,1024)
    const float* index  = (const float*)d_in[3];   // (2048,1)
    float* out = (float*)d_out;                    // targets(64*1024) ++ importances(64)

    k_reset<<<1, 128>>>();
    mega<<<NB, NT>>>(states, mr, memin, index, out);
}